// round 1
// baseline (speedup 1.0000x reference)
#include <cuda_runtime.h>
#include <cuda_bf16.h>

#define LEN 8192      // L
#define NROWS 8192    // B*C = 32*256
#define NT 256        // threads per block
#define SEG 32        // LEN / NT
#define PAD(i) ((i) + ((i) >> 5))   // pad 1 float per 32 -> conflict-free strided access
#define SMEM_FLOATS (2 * (LEN + (LEN >> 5)) + 2 * NT)

// Precomputed per-index coefficients (scratch via __device__ globals; no allocs)
__device__ float g_a[LEN];     // a[i] = -sup[i+1]/diag[i]  (a[L-1] = 0)
__device__ float g_rinv[LEN];  // 1/diag[i]

__global__ void ou_coef_kernel(const float* __restrict__ diag,
                               const float* __restrict__ sup) {
    int i = blockIdx.x * blockDim.x + threadIdx.x;
    if (i < LEN) {
        float rinv = 1.0f / diag[i];
        g_rinv[i] = rinv;
        float e = (i < LEN - 1) ? sup[i + 1] : 0.0f;
        g_a[i] = -e * rinv;
    }
}

// One block per row: affine-scan backward substitution.
// x[i] = a[i]*x[i+1] + b[i],  b[i] = z[i]/diag[i],  x beyond end = 0.
__global__ __launch_bounds__(NT) void ou_solve_kernel(const float* __restrict__ z,
                                                      float* __restrict__ x) {
    extern __shared__ float smem[];
    float* sa    = smem;                                 // LEN + LEN/32
    float* sb    = sa + (LEN + (LEN >> 5));              // LEN + LEN/32 (b, then x in-place)
    float* scanA = sb + (LEN + (LEN >> 5));              // NT
    float* scanB = scanA + NT;                           // NT

    const int tid = threadIdx.x;
    const size_t row = blockIdx.x;
    const float* __restrict__ zr = z + row * (size_t)LEN;
    float* __restrict__ xr = x + row * (size_t)LEN;

    // Coalesced load: z (DRAM), coefficients (L2-resident). Fold rinv into b.
    #pragma unroll
    for (int k = tid; k < LEN; k += NT) {
        float a = g_a[k];
        float b = zr[k] * g_rinv[k];
        int p = PAD(k);
        sa[p] = a;
        sb[p] = b;
    }
    __syncthreads();

    // Phase 1: each thread composes its SEG-element segment (reverse order).
    // Map M_t: x_in -> A*x_in + B  such that x[lo] = M_t(x[hi+1]).
    const int lo = tid * SEG;
    const int hi = lo + SEG - 1;
    float A, B;
    {
        int p = PAD(hi);
        A = sa[p];
        B = sb[p];
    }
    #pragma unroll
    for (int i = hi - 1; i >= lo; --i) {
        int p = PAD(i);
        float ai = sa[p];
        float bi = sb[p];
        A = ai * A;                 // independent chain 1
        B = fmaf(ai, B, bi);        // independent chain 2
    }
    scanA[tid] = A;
    scanB[tid] = B;
    __syncthreads();

    // Phase 2: Kogge-Stone reverse inclusive scan of affine maps.
    // S(t) = M_t o M_{t+1} o ... o M_{NT-1}
    #pragma unroll
    for (int d = 1; d < NT; d <<= 1) {
        float An = 1.0f, Bn = 0.0f;   // identity beyond the end
        if (tid + d < NT) {
            An = scanA[tid + d];
            Bn = scanB[tid + d];
        }
        __syncthreads();
        float At = scanA[tid];
        float Bt = scanB[tid];
        scanA[tid] = At * An;               // S_new = S_old(t) o S_old(t+d)
        scanB[tid] = fmaf(At, Bn, Bt);
        __syncthreads();
    }

    // Incoming boundary value for this segment: x[(t+1)*SEG] = S(t+1)(0) = scanB[t+1]
    float xv = (tid == NT - 1) ? 0.0f : scanB[tid + 1];

    // Phase 3: replay segment with exact boundary value; write x over b in-place.
    #pragma unroll
    for (int i = hi; i >= lo; --i) {
        int p = PAD(i);
        xv = fmaf(sa[p], xv, sb[p]);
        sb[p] = xv;
    }
    __syncthreads();

    // Coalesced store.
    #pragma unroll
    for (int k = tid; k < LEN; k += NT) {
        xr[k] = sb[PAD(k)];
    }
}

extern "C" void kernel_launch(void* const* d_in, const int* in_sizes, int n_in,
                              void* d_out, int out_size) {
    const float* normal_samples = (const float*)d_in[0];  // (32, 256, 8192) f32
    const float* diag           = (const float*)d_in[1];  // (8192,) f32
    const float* sup            = (const float*)d_in[2];  // (8192,) f32
    float* out = (float*)d_out;

    (void)in_sizes; (void)n_in; (void)out_size;

    static_assert(SMEM_FLOATS * sizeof(float) == 69632, "smem size");
    cudaFuncSetAttribute(ou_solve_kernel,
                         cudaFuncAttributeMaxDynamicSharedMemorySize,
                         SMEM_FLOATS * (int)sizeof(float));

    ou_coef_kernel<<<(LEN + NT - 1) / NT, NT>>>(diag, sup);
    ou_solve_kernel<<<NROWS, NT, SMEM_FLOATS * sizeof(float)>>>(normal_samples, out);
}

// round 2
// speedup vs baseline: 1.8229x; 1.8229x over previous
#include <cuda_runtime.h>
#include <cuda_bf16.h>

#define LEN 8192      // L
#define NROWS 8192    // B*C
#define NT 1024       // threads per CTA
#define SEG 8         // LEN / NT, elements per thread
#define GRID 144      // persistent CTAs (<= SM count on B300/GB300)

// Row-invariant coefficients (scratch via __device__ globals; no allocs)
__device__ float g_a[LEN];     // a[i] = -sup[i+1]/diag[i]  (a[L-1] = 0)
__device__ float g_rinv[LEN];  // 1/diag[i]

__global__ void ou_coef_kernel(const float* __restrict__ diag,
                               const float* __restrict__ sup) {
    int i = blockIdx.x * blockDim.x + threadIdx.x;
    if (i < LEN) {
        float rinv = 1.0f / diag[i];
        g_rinv[i] = rinv;
        float e = (i < LEN - 1) ? sup[i + 1] : 0.0f;
        g_a[i] = -e * rinv;
    }
}

// Persistent CTAs; thread t always owns elements [8t, 8t+8) of every row it
// touches, so the per-element affine coefficients stay in registers for the
// whole kernel. Per row: register segment compose -> warp shfl reverse scan
// -> warp0 scans 32 warp aggregates -> register replay. No bulk shared memory.
__global__ __launch_bounds__(NT, 1) void ou_solve_kernel(const float* __restrict__ z,
                                                         float* __restrict__ x) {
    __shared__ float aggA[32];
    __shared__ float aggB[32];
    __shared__ float inclB[32];   // inclusive suffix (B component) of warp aggregates

    const int tid  = threadIdx.x;
    const int lane = tid & 31;
    const int warp = tid >> 5;

    // Coefficients for this thread's fixed segment: registers, loaded once.
    const float4 ca0 = *(const float4*)(g_a    + tid * SEG);
    const float4 ca1 = *(const float4*)(g_a    + tid * SEG + 4);
    const float4 cr0 = *(const float4*)(g_rinv + tid * SEG);
    const float4 cr1 = *(const float4*)(g_rinv + tid * SEG + 4);

    const size_t tseg = (size_t)tid * SEG;

    // Prefetch first row's z
    int row = blockIdx.x;
    float4 nz0, nz1;
    {
        const float* zr = z + (size_t)row * LEN + tseg;
        nz0 = *(const float4*)(zr);
        nz1 = *(const float4*)(zr + 4);
    }

    for (; row < NROWS; row += GRID) {
        float4 z0 = nz0, z1 = nz1;
        // Prefetch next row early to cover DRAM latency across the scan.
        int nrow = row + GRID;
        if (nrow < NROWS) {
            const float* zr = z + (size_t)nrow * LEN + tseg;
            nz0 = *(const float4*)(zr);
            nz1 = *(const float4*)(zr + 4);
        }

        // b[i] = z[i] / diag[i]
        float b0 = z0.x * cr0.x, b1 = z0.y * cr0.y, b2 = z0.z * cr0.z, b3 = z0.w * cr0.w;
        float b4 = z1.x * cr1.x, b5 = z1.y * cr1.y, b6 = z1.z * cr1.z, b7 = z1.w * cr1.w;

        // Segment composition (reverse): x[lo] = A * x[hi+1] + B.
        // Two independent chains (A: MUL, B: FMA).
        float A = ca1.w, B = b7;
        B = fmaf(ca1.z, B, b6); A *= ca1.z;
        B = fmaf(ca1.y, B, b5); A *= ca1.y;
        B = fmaf(ca1.x, B, b4); A *= ca1.x;
        B = fmaf(ca0.w, B, b3); A *= ca0.w;
        B = fmaf(ca0.z, B, b2); A *= ca0.z;
        B = fmaf(ca0.y, B, b1); A *= ca0.y;
        B = fmaf(ca0.x, B, b0); A *= ca0.x;

        // Warp-level reverse inclusive scan of affine maps:
        // S(l) = M_l o M_{l+1} o ... o M_31
        float sA = A, sB = B;
        #pragma unroll
        for (int d = 1; d < 32; d <<= 1) {
            float A2 = __shfl_down_sync(0xffffffffu, sA, d);
            float B2 = __shfl_down_sync(0xffffffffu, sB, d);
            if (lane + d < 32) {
                sB = fmaf(sA, B2, sB);   // uses old sA
                sA = sA * A2;
            }
        }
        if (lane == 0) { aggA[warp] = sA; aggB[warp] = sB; }
        __syncthreads();

        // Warp 0: reverse inclusive scan of the 32 warp aggregates.
        if (warp == 0) {
            float gA = aggA[lane], gB = aggB[lane];
            #pragma unroll
            for (int d = 1; d < 32; d <<= 1) {
                float A2 = __shfl_down_sync(0xffffffffu, gA, d);
                float B2 = __shfl_down_sync(0xffffffffu, gB, d);
                if (lane + d < 32) {
                    gB = fmaf(gA, B2, gB);
                    gA = gA * A2;
                }
            }
            inclB[lane] = gB;
        }
        __syncthreads();

        // T_w = exclusive suffix for warp w (evaluated at 0 -> only B needed).
        float T_B = (warp < 31) ? inclB[warp + 1] : 0.0f;
        // Final scan value (B component) at this thread.
        float B_f = fmaf(sA, T_B, sB);
        // Boundary x entering this segment = B_final(t+1).
        float xv = __shfl_down_sync(0xffffffffu, B_f, 1);
        if (lane == 31) xv = T_B;   // next thread is lane0 of warp+1 -> its final B = T_B

        // Replay segment in registers; pack and store.
        float4 o0, o1;
        xv = fmaf(ca1.w, xv, b7); o1.w = xv;
        xv = fmaf(ca1.z, xv, b6); o1.z = xv;
        xv = fmaf(ca1.y, xv, b5); o1.y = xv;
        xv = fmaf(ca1.x, xv, b4); o1.x = xv;
        xv = fmaf(ca0.w, xv, b3); o0.w = xv;
        xv = fmaf(ca0.z, xv, b2); o0.z = xv;
        xv = fmaf(ca0.y, xv, b1); o0.y = xv;
        xv = fmaf(ca0.x, xv, b0); o0.x = xv;

        float* xr = x + (size_t)row * LEN + tseg;
        *(float4*)(xr)     = o0;
        *(float4*)(xr + 4) = o1;
    }
}

extern "C" void kernel_launch(void* const* d_in, const int* in_sizes, int n_in,
                              void* d_out, int out_size) {
    const float* normal_samples = (const float*)d_in[0];  // (32, 256, 8192) f32
    const float* diag           = (const float*)d_in[1];  // (8192,) f32
    const float* sup            = (const float*)d_in[2];  // (8192,) f32
    float* out = (float*)d_out;

    (void)in_sizes; (void)n_in; (void)out_size;

    ou_coef_kernel<<<(LEN + 255) / 256, 256>>>(diag, sup);
    ou_solve_kernel<<<GRID, NT>>>(normal_samples, out);
}